// round 2
// baseline (speedup 1.0000x reference)
#include <cuda_runtime.h>
#include <cstdint>
#include <cmath>

#define NN   512
#define KK   32
#define PP   1024
#define QQ   512
#define MM   2048
#define RHO        0.70710678118654752f
#define KAPPA_DIAG 0.45f
#define TOL        3e-6f
#define MITR       300

// scratch (static device globals; no allocation)
__device__ __align__(128) float g_ZT[MM * NN];   // Z^T : [m][n]
__device__ __align__(128) float g_XT[MM * NN];   // X^T : [m][n]
__device__ float g_scales[3];                    // sL, sR, sD

// ---------------------------------------------------------------------------
// Kernel 1: projection scale factors (1 CTA, 512 threads)
// ---------------------------------------------------------------------------
__global__ void scales_kernel(const float* __restrict__ L,
                              const float* __restrict__ R,
                              const float* __restrict__ Dg)
{
    __shared__ float red[NN];
    int t = threadIdx.x;

    // L row sums (inf norm of L)
    float s = 0.f;
#pragma unroll
    for (int k = 0; k < KK; ++k) s += fabsf(L[t * KK + k]);
    red[t] = s;
    __syncthreads();
    for (int h = 256; h > 0; h >>= 1) {
        if (t < h) red[t] = fmaxf(red[t], red[t + h]);
        __syncthreads();
    }
    if (t == 0) {
        float nl = red[0];
        g_scales[0] = (nl > RHO) ? (RHO / nl) : 1.0f;
    }
    __syncthreads();

    // R column sums (inf norm of R^T): t = part*32 + k, 16 parts of 32 rows
    {
        int k = t & 31, part = t >> 5;
        float cs = 0.f;
        int n0 = part * 32;
        for (int n = n0; n < n0 + 32; ++n) cs += fabsf(R[n * KK + k]);
        red[t] = cs;
    }
    __syncthreads();
    if (t < 32) {
        float cs = 0.f;
#pragma unroll
        for (int p = 0; p < 16; ++p) cs += red[p * 32 + t];
#pragma unroll
        for (int off = 16; off > 0; off >>= 1)
            cs = fmaxf(cs, __shfl_xor_sync(0xffffffffu, cs, off));
        if (t == 0) g_scales[1] = (cs > RHO) ? (RHO / cs) : 1.0f;
    }
    __syncthreads();

    // Diag max-abs
    red[t] = fabsf(Dg[t]);
    __syncthreads();
    for (int h = 256; h > 0; h >>= 1) {
        if (t < h) red[t] = fmaxf(red[t], red[t + h]);
        __syncthreads();
    }
    if (t == 0) {
        float dm = red[0];
        g_scales[2] = (dm > KAPPA_DIAG) ? (KAPPA_DIAG / dm) : 1.0f;
    }
}

// ---------------------------------------------------------------------------
// Kernel 2/4: C[m][j] = sum_k A0[m][k]*B0[j][k]  (+ sum_k A1[m][k]*B1[j][k])
// BM=128, BN=64, BK=16, 256 threads, 8x4 microtile. All dims exact multiples.
// ---------------------------------------------------------------------------
__global__ __launch_bounds__(256)
void gemm_tn_kernel(const float* __restrict__ A0, int lda0,
                    const float* __restrict__ B0, int ldb0, int K0,
                    const float* __restrict__ A1, int lda1,
                    const float* __restrict__ B1, int ldb1, int K1,
                    float* __restrict__ Cm, int ldc)
{
    __shared__ float As[16][132];
    __shared__ float Bs[16][68];

    int t  = threadIdx.x;
    int bm = blockIdx.x * 128;
    int bn = blockIdx.y * 64;
    int ty = t >> 4;       // 0..15
    int tx = t & 15;       // 0..15

    float acc[8][4];
#pragma unroll
    for (int i = 0; i < 8; ++i)
#pragma unroll
        for (int j = 0; j < 4; ++j) acc[i][j] = 0.f;

    for (int ph = 0; ph < 2; ++ph) {
        const float* A = ph ? A1 : A0;
        const float* B = ph ? B1 : B0;
        int lda = ph ? lda1 : lda0;
        int ldb = ph ? ldb1 : ldb0;
        int K   = ph ? K1 : K0;
        if (K == 0) continue;

        for (int kt = 0; kt < K; kt += 16) {
            __syncthreads();
            {   // A tile 128x16 -> As[k][m]
                int m  = t >> 2;
                int kq = (t & 3) * 4;
                float4 v = *(const float4*)&A[(size_t)(bm + m) * lda + kt + kq];
                As[kq + 0][m] = v.x; As[kq + 1][m] = v.y;
                As[kq + 2][m] = v.z; As[kq + 3][m] = v.w;
                int m2 = m + 64;
                float4 w = *(const float4*)&A[(size_t)(bm + m2) * lda + kt + kq];
                As[kq + 0][m2] = w.x; As[kq + 1][m2] = w.y;
                As[kq + 2][m2] = w.z; As[kq + 3][m2] = w.w;
            }
            {   // B tile 64x16 -> Bs[k][j]
                int jn = t >> 2;
                int kq = (t & 3) * 4;
                float4 v = *(const float4*)&B[(size_t)(bn + jn) * ldb + kt + kq];
                Bs[kq + 0][jn] = v.x; Bs[kq + 1][jn] = v.y;
                Bs[kq + 2][jn] = v.z; Bs[kq + 3][jn] = v.w;
            }
            __syncthreads();
#pragma unroll
            for (int k = 0; k < 16; ++k) {
                float4 a0 = *(const float4*)&As[k][ty * 8];
                float4 a1 = *(const float4*)&As[k][ty * 8 + 4];
                float4 b  = *(const float4*)&Bs[k][tx * 4];
                float av[8] = {a0.x, a0.y, a0.z, a0.w, a1.x, a1.y, a1.z, a1.w};
                float bv[4] = {b.x, b.y, b.z, b.w};
#pragma unroll
                for (int i = 0; i < 8; ++i)
#pragma unroll
                    for (int j = 0; j < 4; ++j)
                        acc[i][j] = fmaf(av[i], bv[j], acc[i][j]);
            }
        }
    }

#pragma unroll
    for (int i = 0; i < 8; ++i) {
        float4 v = make_float4(acc[i][0], acc[i][1], acc[i][2], acc[i][3]);
        *(float4*)&Cm[(size_t)(bm + ty * 8 + i) * ldc + bn + tx * 4] = v;
    }
}

// ---------------------------------------------------------------------------
// Kernel 3: per-column Picard fixed point  x = relu(s*L(R^T x) + Dp.*x + z)
// 512 threads = 16 warps = 16 columns per CTA; grid = 128 CTAs (one wave).
// L^T, R^T in SMEM as [32][512] (conflict-free: bank = n % 32 = lane).
// ---------------------------------------------------------------------------
__global__ __launch_bounds__(512, 1)
void fixed_point_kernel(const float* __restrict__ L,
                        const float* __restrict__ R,
                        const float* __restrict__ Dg)
{
    extern __shared__ float sm[];
    float* Lt = sm;                 // [32][512]
    float* Rt = sm + KK * NN;       // [32][512]
    float* Dp = sm + 2 * KK * NN;   // [512]

    int t = threadIdx.x;
    float sD = g_scales[2];
    float s  = g_scales[0] * g_scales[1];

#pragma unroll
    for (int k = 0; k < KK; ++k) {
        Lt[k * NN + t] = L[t * KK + k];
        Rt[k * NN + t] = R[t * KK + k];
    }
    Dp[t] = Dg[t] * sD;
    __syncthreads();

    int lane = t & 31;
    int wid  = t >> 5;
    int m    = blockIdx.x * 16 + wid;

    float x[16], z[16];
#pragma unroll
    for (int i = 0; i < 16; ++i) {
        z[i] = g_ZT[(size_t)m * NN + lane + 32 * i];
        x[i] = 0.f;
    }

    for (int iter = 0; iter < MITR; ++iter) {
        // y = R^T x  (partial per lane over its 16 rows, then butterfly-sum)
        float y[KK];
#pragma unroll
        for (int k = 0; k < KK; ++k) {
            float acc = 0.f;
#pragma unroll
            for (int i = 0; i < 16; ++i)
                acc = fmaf(Rt[k * NN + lane + 32 * i], x[i], acc);
            y[k] = acc;
        }
#pragma unroll
        for (int k = 0; k < KK; ++k) {
#pragma unroll
            for (int off = 16; off > 0; off >>= 1)
                y[k] += __shfl_xor_sync(0xffffffffu, y[k], off);
            y[k] *= s;
        }

        // x' = relu(L y + Dp.*x + z), track max |dx|
        float err = 0.f;
#pragma unroll
        for (int i = 0; i < 16; ++i) {
            int n = lane + 32 * i;
            float acc = fmaf(Dp[n], x[i], z[i]);
#pragma unroll
            for (int k = 0; k < KK; ++k)
                acc = fmaf(Lt[k * NN + n], y[k], acc);
            float xn = fmaxf(acc, 0.f);
            err = fmaxf(err, fabsf(xn - x[i]));
            x[i] = xn;
        }
#pragma unroll
        for (int off = 16; off > 0; off >>= 1)
            err = fmaxf(err, __shfl_xor_sync(0xffffffffu, err, off));
        if (err < TOL) break;
    }

#pragma unroll
    for (int i = 0; i < 16; ++i)
        g_XT[(size_t)m * NN + lane + 32 * i] = x[i];
}

// ---------------------------------------------------------------------------
extern "C" void kernel_launch(void* const* d_in, const int* in_sizes, int n_in,
                              void* d_out, int out_size)
{
    (void)in_sizes; (void)n_in; (void)out_size;
    const float* U  = (const float*)d_in[0];   // [M, P]
    const float* L  = (const float*)d_in[1];   // [N, K]
    const float* R  = (const float*)d_in[2];   // [N, K]
    const float* Dg = (const float*)d_in[3];   // [N]
    const float* B  = (const float*)d_in[4];   // [N, P]
    const float* C  = (const float*)d_in[5];   // [Q, N]
    const float* D  = (const float*)d_in[6];   // [Q, P]
    float* out = (float*)d_out;                // [M, Q]

    static int smem_set = 0;
    if (!smem_set) {
        cudaFuncSetAttribute(fixed_point_kernel,
                             cudaFuncAttributeMaxDynamicSharedMemorySize,
                             (2 * KK * NN + NN) * sizeof(float));
        smem_set = 1;
    }

    float* zt; cudaGetSymbolAddress((void**)&zt, g_ZT);
    float* xt; cudaGetSymbolAddress((void**)&xt, g_XT);

    // 1) scale factors
    scales_kernel<<<1, 512>>>(L, R, Dg);

    // 2) ZT[m][n] = sum_p U[m,p] * B[n,p]
    gemm_tn_kernel<<<dim3(MM / 128, NN / 64), 256>>>(
        U, PP, B, PP, PP,
        U, PP, B, PP, 0,
        zt, NN);

    // 3) fixed point -> XT
    fixed_point_kernel<<<MM / 16, 512, (2 * KK * NN + NN) * sizeof(float)>>>(L, R, Dg);

    // 4) out[m][q] = sum_n XT[m,n]*C[q,n] + sum_p U[m,p]*D[q,p]
    gemm_tn_kernel<<<dim3(MM / 128, QQ / 64), 256>>>(
        xt, NN, C, NN, NN,
        U,  PP, D, PP, PP,
        out, QQ);
}